// round 6
// baseline (speedup 1.0000x reference)
#include <cuda_runtime.h>
#include <cstdint>

#define N_NODES  100000
#define N_EDGES  1200000
#define N_GRAPHS 1024
#define F        64
#define BN_EPS   1e-5f
#define SCAN_BLOCKS 98          // ceil(100000/1024)

// ---------------- device scratch (no allocations allowed) ----------------
__device__ float4 g_agg4[N_NODES * (F / 4)];   // neighbor MEANS (fully overwritten)
__device__ int    g_cnt[N_NODES];              // in-degree
__device__ int    g_off[N_NODES];              // CSR offsets (exclusive scan of cnt)
__device__ int    g_cursor[N_NODES];           // scatter cursors
__device__ int    g_esrc[N_EDGES];             // src ids grouped by dst
__device__ int    g_scan_pack[SCAN_BLOCKS];    // lookback: (sum<<2)|flag, flag:0/1=agg/2=incl
__device__ int    g_hg[N_GRAPHS * F];          // per-graph max, float bits as int

// ---------------- f32x2 packed helpers ----------------
__device__ __forceinline__ unsigned long long pack2(float x) {
    unsigned long long r;
    asm("mov.b64 %0, {%1, %1};" : "=l"(r) : "f"(x));
    return r;
}
__device__ __forceinline__ void ffma2(unsigned long long& d,
                                      unsigned long long a,
                                      unsigned long long b) {
    asm("fma.rn.f32x2 %0, %1, %2, %0;" : "+l"(d) : "l"(a), "l"(b));
}
__device__ __forceinline__ void unpack2(unsigned long long v, float& lo, float& hi) {
    asm("mov.b64 {%0, %1}, %2;" : "=f"(lo), "=f"(hi) : "l"(v));
}

// ---------------- init: zero counters + flags + readout (small) ----------------
__global__ void k_init() {
    int i = blockIdx.x * blockDim.x + threadIdx.x;
    int stride = gridDim.x * blockDim.x;
    int4 zi = make_int4(0, 0, 0, 0);
    int4* cnt4 = (int4*)g_cnt;                         // 100000 % 4 == 0
    for (int t = i; t < N_NODES / 4; t += stride) cnt4[t] = zi;
    int4* hg4 = (int4*)g_hg;
    for (int t = i; t < N_GRAPHS * F / 4; t += stride) hg4[t] = zi;  // 0 == +0.0f bits
    if (i < SCAN_BLOCKS) g_scan_pack[i] = 0;
}

// ---------------- degree histogram ----------------
__global__ void k_hist(const int* __restrict__ dst) {
    int e = blockIdx.x * blockDim.x + threadIdx.x;
    if (e < N_EDGES) atomicAdd(&g_cnt[dst[e]], 1);
}

// ---------------- single-pass exclusive scan (decoupled lookback) ----------------
__global__ void __launch_bounds__(1024) k_scan() {
    __shared__ int s[1024];
    __shared__ int s_exc;     // exclusive prefix of this block
    int tid = threadIdx.x;
    int b = blockIdx.x;
    int i = b * 1024 + tid;
    int v = (i < N_NODES) ? g_cnt[i] : 0;
    s[tid] = v;
    __syncthreads();
#pragma unroll
    for (int d = 1; d < 1024; d <<= 1) {
        int t = (tid >= d) ? s[tid - d] : 0;
        __syncthreads();
        s[tid] += t;
        __syncthreads();
    }
    int total = s[1023];   // block aggregate (inclusive of all 1024)

    if (tid == 0) {
        if (b == 0) {
            atomicExch(&g_scan_pack[0], (total << 2) | 2);  // inclusive known
            s_exc = 0;
        } else {
            atomicExch(&g_scan_pack[b], (total << 2) | 1);  // aggregate ready
            // look back
            int running = 0;
            int p = b - 1;
            while (true) {
                int w;
                do { w = atomicAdd(&g_scan_pack[p], 0); } while ((w & 3) == 0);
                running += (w >> 2);
                if ((w & 3) == 2) break;
                p--;
            }
            atomicExch(&g_scan_pack[b], ((running + total) << 2) | 2);
            s_exc = running;
        }
    }
    __syncthreads();
    if (i < N_NODES) {
        int off = s[tid] - v + s_exc;    // global exclusive prefix
        g_off[i] = off;
        g_cursor[i] = off;
    }
}

// ---------------- scatter: bucket src ids by dst ----------------
__global__ void k_scatter(const int* __restrict__ src, const int* __restrict__ dst) {
    int e = blockIdx.x * blockDim.x + threadIdx.x;
    if (e < N_EDGES) {
        int p = atomicAdd(&g_cursor[dst[e]], 1);
        g_esrc[p] = src[e];
    }
}

// ---------------- gather-aggregate: mean of neighbor feats ----------------
// 16 threads per node; thread q owns float4 column q. 4-deep unroll -> MLP=4.
__global__ void __launch_bounds__(256) k_gather(const float4* __restrict__ feats4) {
    int t = blockIdx.x * 256 + threadIdx.x;
    int node = t >> 4;
    int q = t & 15;
    if (node >= N_NODES) return;
    int start = g_off[node];
    int n = g_cnt[node];
    const int* ep = &g_esrc[start];

    float4 a0 = make_float4(0.f, 0.f, 0.f, 0.f);
    float4 a1 = a0, a2 = a0, a3 = a0;

    int i = 0;
    for (; i + 4 <= n; i += 4) {
        int s0 = ep[i], s1 = ep[i + 1], s2 = ep[i + 2], s3 = ep[i + 3];
        float4 v0 = feats4[(long long)s0 * 16 + q];
        float4 v1 = feats4[(long long)s1 * 16 + q];
        float4 v2 = feats4[(long long)s2 * 16 + q];
        float4 v3 = feats4[(long long)s3 * 16 + q];
        a0.x += v0.x; a0.y += v0.y; a0.z += v0.z; a0.w += v0.w;
        a1.x += v1.x; a1.y += v1.y; a1.z += v1.z; a1.w += v1.w;
        a2.x += v2.x; a2.y += v2.y; a2.z += v2.z; a2.w += v2.w;
        a3.x += v3.x; a3.y += v3.y; a3.z += v3.z; a3.w += v3.w;
    }
    for (; i < n; i++) {
        int s = ep[i];
        float4 v = feats4[(long long)s * 16 + q];
        a0.x += v.x; a0.y += v.y; a0.z += v.z; a0.w += v.w;
    }
    float4 acc;
    acc.x = (a0.x + a1.x) + (a2.x + a3.x);
    acc.y = (a0.y + a1.y) + (a2.y + a3.y);
    acc.z = (a0.z + a1.z) + (a2.z + a3.z);
    acc.w = (a0.w + a1.w) + (a2.w + a3.w);
    float inv = 1.0f / (float)max(n, 1);
    acc.x *= inv; acc.y *= inv; acc.z *= inv; acc.w *= inv;
    g_agg4[(long long)node * 16 + q] = acc;  // stores the MEAN
}

// ---------------- node update + relu + per-graph max readout ----------------
__global__ void __launch_bounds__(256)
k_node(const float4* __restrict__ feats4,
       const float*  __restrict__ Wself,
       const float*  __restrict__ Wneigh,
       const float*  __restrict__ bneigh,
       const int*    __restrict__ gids) {
    __shared__ float sWs[F * F];
    __shared__ float sWn[F * F];
    for (int i = threadIdx.x; i < F * F; i += 256) {
        sWs[i] = Wself[i];
        sWn[i] = Wneigh[i];
    }
    __syncthreads();

    int node = blockIdx.x * 256 + threadIdx.x;
    if (node >= N_NODES) return;

    unsigned long long h2[F / 2];
#pragma unroll
    for (int o = 0; o < F / 2; o++) h2[o] = 0ULL;

#pragma unroll
    for (int kk = 0; kk < 16; kk++) {
        float4 fs = feats4[(long long)node * 16 + kk];
        float4 fm = g_agg4[(long long)node * 16 + kk];   // already the mean
        float xs[4] = {fs.x, fs.y, fs.z, fs.w};
        float xm[4] = {fm.x, fm.y, fm.z, fm.w};
#pragma unroll
        for (int j = 0; j < 4; j++) {
            int k = kk * 4 + j;
            unsigned long long xs2 = pack2(xs[j]);
            unsigned long long xm2 = pack2(xm[j]);
            const ulonglong2* wsr = (const ulonglong2*)&sWs[k * F];
            const ulonglong2* wnr = (const ulonglong2*)&sWn[k * F];
#pragma unroll
            for (int o4 = 0; o4 < 16; o4++) {
                ulonglong2 ws = wsr[o4];   // LDS.128, warp-broadcast
                ulonglong2 wn = wnr[o4];
                ffma2(h2[o4 * 2 + 0], xs2, ws.x);
                ffma2(h2[o4 * 2 + 0], xm2, wn.x);
                ffma2(h2[o4 * 2 + 1], xs2, ws.y);
                ffma2(h2[o4 * 2 + 1], xm2, wn.y);
            }
        }
    }

    int g = gids[node];
#pragma unroll
    for (int o2 = 0; o2 < F / 2; o2++) {
        float lo, hi;
        unpack2(h2[o2], lo, hi);
        float v0 = fmaxf(lo + bneigh[o2 * 2 + 0], 0.0f);   // relu; >= 0
        float v1 = fmaxf(hi + bneigh[o2 * 2 + 1], 0.0f);
        atomicMax(&g_hg[g * F + o2 * 2 + 0], __float_as_int(v0));
        atomicMax(&g_hg[g * F + o2 * 2 + 1], __float_as_int(v1));
    }
}

// ---------------- MLP head: one warp per graph, no block syncs ----------------
__global__ void __launch_bounds__(128)
k_mlp(const float* __restrict__ W1, const float* __restrict__ b1,
      const float* __restrict__ g1, const float* __restrict__ be1,
      const float* __restrict__ rm1, const float* __restrict__ rv1,
      const float* __restrict__ W2, const float* __restrict__ b2,
      const float* __restrict__ g2, const float* __restrict__ be2,
      const float* __restrict__ rm2, const float* __restrict__ rv2,
      const float* __restrict__ W3, const float* __restrict__ b3,
      float* __restrict__ out) {
    __shared__ float sh[4][F];     // per-warp layer-0 input
    __shared__ float sy[4][128];   // per-warp layer-1 output

    int w = threadIdx.x >> 5;
    int lane = threadIdx.x & 31;
    int g = blockIdx.x * 4 + w;

    sh[w][lane]      = __int_as_float(g_hg[g * F + lane]);
    sh[w][lane + 32] = __int_as_float(g_hg[g * F + lane + 32]);
    __syncwarp();

    // layer 1: 64 -> 128; lane computes outputs j = lane + 32*m
    float a0 = b1[lane], a1 = b1[lane + 32], a2 = b1[lane + 64], a3 = b1[lane + 96];
#pragma unroll 8
    for (int k = 0; k < F; k++) {
        float xv = sh[w][k];                    // LDS broadcast
        const float* wr = &W1[k * 128 + lane];  // coalesced 512B per k
        a0 = fmaf(xv, wr[0],  a0);
        a1 = fmaf(xv, wr[32], a1);
        a2 = fmaf(xv, wr[64], a2);
        a3 = fmaf(xv, wr[96], a3);
    }
    {
        float acc[4] = {a0, a1, a2, a3};
#pragma unroll
        for (int m = 0; m < 4; m++) {
            int j = lane + 32 * m;
            float a = fmaxf(acc[m], 0.0f);
            a = (a - rm1[j]) * rsqrtf(rv1[j] + BN_EPS) * g1[j] + be1[j];
            sy[w][j] = a;
        }
    }
    __syncwarp();

    // layer 2: 128 -> 64; lane computes outputs j = lane, lane+32
    float c0 = b2[lane], c1 = b2[lane + 32];
#pragma unroll 8
    for (int k = 0; k < 128; k++) {
        float yv = sy[w][k];                    // LDS broadcast
        const float* wr = &W2[k * F + lane];    // coalesced 256B per k
        c0 = fmaf(yv, wr[0],  c0);
        c1 = fmaf(yv, wr[32], c1);
    }
    float p;
    {
        int j0 = lane, j1 = lane + 32;
        float x0 = fmaxf(c0, 0.0f);
        x0 = (x0 - rm2[j0]) * rsqrtf(rv2[j0] + BN_EPS) * g2[j0] + be2[j0];
        float x1 = fmaxf(c1, 0.0f);
        x1 = (x1 - rm2[j1]) * rsqrtf(rv2[j1] + BN_EPS) * g2[j1] + be2[j1];
        p = x0 * W3[j0] + x1 * W3[j1];
    }
#pragma unroll
    for (int off = 16; off > 0; off >>= 1)
        p += __shfl_down_sync(0xFFFFFFFFu, p, off);
    if (lane == 0) out[g] = p + b3[0];
}

// ---------------- launcher ----------------
extern "C" void kernel_launch(void* const* d_in, const int* in_sizes, int n_in,
                              void* d_out, int out_size) {
    const float4* feats4 = (const float4*)d_in[0];
    const int*    src    = (const int*)d_in[1];
    const int*    dst    = (const int*)d_in[2];
    const int*    gids   = (const int*)d_in[3];
    const float*  Wself  = (const float*)d_in[4];
    const float*  Wneigh = (const float*)d_in[5];
    const float*  bneigh = (const float*)d_in[6];
    const float*  W1  = (const float*)d_in[7];
    const float*  b1  = (const float*)d_in[8];
    const float*  g1  = (const float*)d_in[9];
    const float*  be1 = (const float*)d_in[10];
    const float*  rm1 = (const float*)d_in[11];
    const float*  rv1 = (const float*)d_in[12];
    const float*  W2  = (const float*)d_in[13];
    const float*  b2  = (const float*)d_in[14];
    const float*  g2  = (const float*)d_in[15];
    const float*  be2 = (const float*)d_in[16];
    const float*  rm2 = (const float*)d_in[17];
    const float*  rv2 = (const float*)d_in[18];
    const float*  W3  = (const float*)d_in[19];
    const float*  b3  = (const float*)d_in[20];
    float* out = (float*)d_out;

    k_init<<<296, 256>>>();
    k_hist<<<(N_EDGES + 255) / 256, 256>>>(dst);
    k_scan<<<SCAN_BLOCKS, 1024>>>();
    k_scatter<<<(N_EDGES + 255) / 256, 256>>>(src, dst);
    k_gather<<<(N_NODES * 16 + 255) / 256, 256>>>(feats4);
    k_node<<<(N_NODES + 255) / 256, 256>>>(feats4, Wself, Wneigh, bneigh, gids);
    k_mlp<<<N_GRAPHS / 4, 128>>>(W1, b1, g1, be1, rm1, rv1,
                                 W2, b2, g2, be2, rm2, rv2,
                                 W3, b3, out);
}